// round 4
// baseline (speedup 1.0000x reference)
#include <cuda_runtime.h>

#define MAX_NODES 100352

// Scratch (no cudaMalloc allowed): per-node packed params and coordination counts.
__device__ float4 g_params[MAX_NODES];
__device__ int    g_cn[MAX_NODES];

// GNB table, only columns 2 (R) and 3 (C6) are ever used by the reference.
__constant__ float2 c_tab[87] = {
    {0.f,0.f},
    {3.6516f,95.99f},{2.1843f,40.67f},{1.2711f,70.21f},{3.3497f,114.51f},
    {2.7079f,152.36f},{1.8219f,184.28f},{2.4667f,482.54f},{2.365f,405.57f},
    {1.5062f,218.45f},{1.8233f,174.81f},{1.3974f,181.7f},{3.3515f,263.02f},
    {3.0102f,228.1f},{3.1629f,359.43f},{3.2554f,3222.12f},{2.9539f,2144.49f},
    {3.0368f,2072.46f},{2.6598f,1357.42f},{4.0877f,1406.65f},{4.1275f,1058.36f},
    {9.7282f,11498.73f},{8.5322f,3361.33f},{7.2344f,2095.91f},{5.3605f,1049.31f},
    {3.718f,966.27f},{3.6408f,1571.36f},{3.4961f,1183.59f},{3.5108f,787.76f},
    {3.0537f,563.93f},{3.0261f,592.91f},{3.1735f,430.82f},{3.1773f,812.57f},
    {3.8357f,4533.53f},{3.1109f,3440.92f},{3.2122f,3859.82f},{2.8263f,2729.6f},
    {2.412f,1864.19f},{1.894f,1175.73f},{11.2061f,32141.18f},{6.821f,27655.14f},
    {7.2367f,2864.2f},{3.901f,3563.45f},{4.0857f,3266.43f},{4.045f,3967.23f},
    {3.4813f,2233.82f},{3.0487f,1393.49f},{2.7795f,1315.09f},{2.8673f,1311.47f},
    {3.3339f,1460.56f},{3.0086f,1662.99f},{3.9919f,8089.97f},{3.4209f,6887.05f},
    {3.5649f,8799.32f},{3.0288f,6136.5f},{2.262f,3757.31f},{1.3837f,2561.18f},
    {12.171f,66580.83f},
    {0.f,0.f},{0.f,0.f},{0.f,0.f},{0.f,0.f},{0.f,0.f},{0.f,0.f},{0.f,0.f},
    {0.f,0.f},{0.f,0.f},{0.f,0.f},{0.f,0.f},{0.f,0.f},{0.f,0.f},{0.f,0.f},
    {6.0791f,27593.76f},{5.7661f,15364.65f},{3.6366f,2734.5f},{4.241f,4801.82f},
    {4.1348f,5685.94f},{3.4213f,2786.0f},{3.2486f,2699.79f},{2.9588f,2282.6f},
    {2.9381f,2476.79f},{2.7711f,2988.7f},{2.5816f,2506.63f},{3.785f,8916.84f},
    {3.5381f,8694.22f},{3.6985f,11821.61f},{3.0551f,8410.64f}
};

__global__ void zero_kernel(float* __restrict__ out, int n) {
    int i = blockIdx.x * blockDim.x + threadIdx.x;
    if (i < n) {
        out[i] = 0.0f;
        g_cn[i] = 0;
    }
}

__global__ void count_kernel(const int* __restrict__ recv, int n4, int n) {
    int i = blockIdx.x * blockDim.x + threadIdx.x;
    if (i < n4) {
        int4 v = reinterpret_cast<const int4*>(recv)[i];
        atomicAdd(&g_cn[v.x], 1);
        atomicAdd(&g_cn[v.y], 1);
        atomicAdd(&g_cn[v.z], 1);
        atomicAdd(&g_cn[v.w], 1);
    } else if (i == n4) {
        for (int j = n4 * 4; j < n; j++) atomicAdd(&g_cn[recv[j]], 1);
    }
}

// Scalar fallback (unaligned / non-multiple-of-4 edge count)
__global__ void count_kernel_scalar(const int* __restrict__ recv, int n) {
    int i = blockIdx.x * blockDim.x + threadIdx.x;
    if (i < n) atomicAdd(&g_cn[recv[i]], 1);
}

__global__ void node_kernel(const int* __restrict__ Z, int n) {
    int i = blockIdx.x * blockDim.x + threadIdx.x;
    if (i < n) {
        int z = Z[i];
        float2 p = c_tab[z];
        int cn = g_cn[i];
        if (z == 6) p = (cn <= 3) ? make_float2(2.2348f, 429.69f)
                                  : make_float2(1.8219f, 184.28f);
        if (z == 7) p = (cn <= 2) ? make_float2(2.6454f, 720.18f)
                                  : make_float2(2.4667f, 482.54f);
        float R = p.x, C6 = p.y;
        float4 o;
        o.x = sqrtf(sqrtf(R)); // R^(1/4): sqrt(R_ij) = o.x_s * o.x_r
        o.y = sqrtf(C6);       // C6_ij   = o.y_s * o.y_r
        o.z = R * R * R;       // R_ij^6  = o.z_s * o.z_r
        o.w = 0.0f;
        g_params[i] = o;
    }
}

__device__ __forceinline__ void edge_one(int s, int t, float r,
                                         float* __restrict__ out) {
    float4 ps = g_params[s];
    float4 pt = g_params[t];
    float sqrtRij = ps.x * pt.x;
    float C6ij    = ps.y * pt.y;
    float Rij6    = ps.z * pt.z;

    float r0 = 0.4f * sqrtRij + 4.0f;
    float q  = __fdividef(r0, r);
    float q2 = q * q, q4 = q2 * q2, q8 = q4 * q4;
    float q14 = q8 * q4 * q2;
    float fd = __fdividef(1.0f, 1.0f + 6.0f * q14);

    float r2 = r * r;
    float r6 = r2 * r2 * r2;
    float e = -C6ij * __fdividef(fd, Rij6 + r6);

    if (r >= 8.0f) {
        float x = (r - 8.0f) * 0.5f;
        float env = 0.0f;
        if (x < 1.0f) {
            float x2 = x * x;
            float x6 = x2 * x2 * x2;
            env = 1.0f + x6 * (-28.0f + x * (48.0f - 21.0f * x));
        }
        e *= env;
    }
    if (e != 0.0f) atomicAdd(&out[t], 0.5f * e);
}

__global__ void edge_kernel(const int* __restrict__ snd,
                            const int* __restrict__ recv,
                            const float* __restrict__ len,
                            float* __restrict__ out, int n4, int n) {
    int i = blockIdx.x * blockDim.x + threadIdx.x;
    if (i < n4) {
        int4   s = reinterpret_cast<const int4*>(snd)[i];
        int4   t = reinterpret_cast<const int4*>(recv)[i];
        float4 r = reinterpret_cast<const float4*>(len)[i];
        edge_one(s.x, t.x, r.x, out);
        edge_one(s.y, t.y, r.y, out);
        edge_one(s.z, t.z, r.z, out);
        edge_one(s.w, t.w, r.w, out);
    } else if (i == n4) {
        for (int j = n4 * 4; j < n; j++) edge_one(snd[j], recv[j], len[j], out);
    }
}

__global__ void edge_kernel_scalar(const int* __restrict__ snd,
                                   const int* __restrict__ recv,
                                   const float* __restrict__ len,
                                   float* __restrict__ out, int n) {
    int i = blockIdx.x * blockDim.x + threadIdx.x;
    if (i < n) edge_one(snd[i], recv[i], len[i], out);
}

extern "C" void kernel_launch(void* const* d_in, const int* in_sizes, int n_in,
                              void* d_out, int out_size) {
    const int*   Z   = (const int*)d_in[0];
    const int*   ei  = (const int*)d_in[1];
    const float* len = (const float*)d_in[2];
    float* out = (float*)d_out;

    int n_nodes = in_sizes[0];
    int n_edges = in_sizes[2];
    const int* snd  = ei;
    const int* recv = ei + n_edges;

    const int TB = 256;
    zero_kernel<<<(n_nodes + TB - 1) / TB, TB>>>(out, n_nodes);

    // Vector path needs receiver half 16B-aligned: true when n_edges % 4 == 0.
    bool vec_ok = ((n_edges & 3) == 0);
    if (vec_ok) {
        int n4 = n_edges >> 2;
        int threads = n4 + 1;  // +1 thread for tail (no-op here)
        count_kernel<<<(threads + TB - 1) / TB, TB>>>(recv, n4, n_edges);
        node_kernel<<<(n_nodes + TB - 1) / TB, TB>>>(Z, n_nodes);
        edge_kernel<<<(threads + TB - 1) / TB, TB>>>(snd, recv, len, out, n4, n_edges);
    } else {
        count_kernel_scalar<<<(n_edges + TB - 1) / TB, TB>>>(recv, n_edges);
        node_kernel<<<(n_nodes + TB - 1) / TB, TB>>>(Z, n_nodes);
        edge_kernel_scalar<<<(n_edges + TB - 1) / TB, TB>>>(snd, recv, len, out, n_edges);
    }
}

// round 5
// speedup vs baseline: 3.0876x; 3.0876x over previous
#include <cuda_runtime.h>
#include <stdint.h>

#define MAX_NODES 100352   // >= 100000, multiple of 16
#define NCLASS 91
#define EDGE_BLOCK 512
#define PERS_GRID 304      // 2 * 152 SMs

// Scratch (no cudaMalloc allowed)
__device__ int     g_cn[MAX_NODES];
__device__ uint8_t g_class[MAX_NODES];  // phase 1: isCN flag; phase 2: class id

// Raw (R, C6) per class. 0..86 = Z rows; 87/88 = C cn<=3 / cn>3; 89/90 = N cn<=2 / cn>2
__constant__ float2 c_raw[NCLASS] = {
    {0.f,0.f},
    {3.6516f,95.99f},{2.1843f,40.67f},{1.2711f,70.21f},{3.3497f,114.51f},
    {2.7079f,152.36f},{1.8219f,184.28f},{2.4667f,482.54f},{2.365f,405.57f},
    {1.5062f,218.45f},{1.8233f,174.81f},{1.3974f,181.7f},{3.3515f,263.02f},
    {3.0102f,228.1f},{3.1629f,359.43f},{3.2554f,3222.12f},{2.9539f,2144.49f},
    {3.0368f,2072.46f},{2.6598f,1357.42f},{4.0877f,1406.65f},{4.1275f,1058.36f},
    {9.7282f,11498.73f},{8.5322f,3361.33f},{7.2344f,2095.91f},{5.3605f,1049.31f},
    {3.718f,966.27f},{3.6408f,1571.36f},{3.4961f,1183.59f},{3.5108f,787.76f},
    {3.0537f,563.93f},{3.0261f,592.91f},{3.1735f,430.82f},{3.1773f,812.57f},
    {3.8357f,4533.53f},{3.1109f,3440.92f},{3.2122f,3859.82f},{2.8263f,2729.6f},
    {2.412f,1864.19f},{1.894f,1175.73f},{11.2061f,32141.18f},{6.821f,27655.14f},
    {7.2367f,2864.2f},{3.901f,3563.45f},{4.0857f,3266.43f},{4.045f,3967.23f},
    {3.4813f,2233.82f},{3.0487f,1393.49f},{2.7795f,1315.09f},{2.8673f,1311.47f},
    {3.3339f,1460.56f},{3.0086f,1662.99f},{3.9919f,8089.97f},{3.4209f,6887.05f},
    {3.5649f,8799.32f},{3.0288f,6136.5f},{2.262f,3757.31f},{1.3837f,2561.18f},
    {12.171f,66580.83f},
    {0.f,0.f},{0.f,0.f},{0.f,0.f},{0.f,0.f},{0.f,0.f},{0.f,0.f},{0.f,0.f},
    {0.f,0.f},{0.f,0.f},{0.f,0.f},{0.f,0.f},{0.f,0.f},{0.f,0.f},{0.f,0.f},
    {6.0791f,27593.76f},{5.7661f,15364.65f},{3.6366f,2734.5f},{4.241f,4801.82f},
    {4.1348f,5685.94f},{3.4213f,2786.0f},{3.2486f,2699.79f},{2.9588f,2282.6f},
    {2.9381f,2476.79f},{2.7711f,2988.7f},{2.5816f,2506.63f},{3.785f,8916.84f},
    {3.5381f,8694.22f},{3.6985f,11821.61f},{3.0551f,8410.64f},
    // 87: C_SP2, 88: C_SP3, 89: N_CN2, 90: N_CN3
    {2.2348f,429.69f},{1.8219f,184.28f},{2.6454f,720.18f},{2.4667f,482.54f}
};

// Phase 0: zero output + cn, and stash is-C/N flag in g_class
__global__ void zero_kernel(float* __restrict__ out, const int* __restrict__ Z, int n) {
    int i = blockIdx.x * blockDim.x + threadIdx.x;
    if (i < n) {
        out[i] = 0.0f;
        g_cn[i] = 0;
        int z = Z[i];
        g_class[i] = (z == 6 || z == 7) ? 1 : 0;
    }
}

// Phase 1: coordination count, but only for C/N receivers (mask cached in smem)
__global__ void __launch_bounds__(EDGE_BLOCK)
count_kernel(const int* __restrict__ recv, int n4, int n) {
    extern __shared__ uint8_t s_mask[];
    {
        const int4* src = (const int4*)g_class;
        int4* dst = (int4*)s_mask;
        for (int j = threadIdx.x; j < MAX_NODES / 16; j += blockDim.x) dst[j] = src[j];
    }
    __syncthreads();
    const int4* r4 = (const int4*)recv;
    int stride = gridDim.x * blockDim.x;
    for (int i = blockIdx.x * blockDim.x + threadIdx.x; i < n4; i += stride) {
        int4 t = r4[i];
        if (s_mask[t.x]) atomicAdd(&g_cn[t.x], 1);
        if (s_mask[t.y]) atomicAdd(&g_cn[t.y], 1);
        if (s_mask[t.z]) atomicAdd(&g_cn[t.z], 1);
        if (s_mask[t.w]) atomicAdd(&g_cn[t.w], 1);
    }
    if (blockIdx.x == 0 && threadIdx.x == 0) {
        for (int j = n4 * 4; j < n; j++) {
            int t = recv[j];
            if (s_mask[t]) atomicAdd(&g_cn[t], 1);
        }
    }
}

// Scalar fallback (recv not 16B aligned)
__global__ void count_kernel_scalar(const int* __restrict__ recv, int n) {
    int i = blockIdx.x * blockDim.x + threadIdx.x;
    if (i < n) {
        int t = recv[i];
        if (g_class[t]) atomicAdd(&g_cn[t], 1);
    }
}

// Phase 2: assign class id per node
__global__ void node_kernel(const int* __restrict__ Z, int n) {
    int i = blockIdx.x * blockDim.x + threadIdx.x;
    if (i < n) {
        int z = Z[i];
        uint8_t c = (uint8_t)z;
        if (z == 6) c = (g_cn[i] <= 3) ? 87 : 88;
        else if (z == 7) c = (g_cn[i] <= 2) ? 89 : 90;
        g_class[i] = c;
    }
}

// Shared edge math: class bytes + 91-entry param table, both in smem
__device__ __forceinline__ void edge_one_sm(const uint8_t* __restrict__ s_cls,
                                            const float4* __restrict__ s_par,
                                            int s, int t, float r,
                                            float* __restrict__ out) {
    int cs = s_cls[s];
    int ct = s_cls[t];
    float4 ps = s_par[cs];
    float4 pt = s_par[ct];
    float sqrtRij = ps.x * pt.x;   // (R_s R_r)^(1/4) = sqrt(R_ij)
    float C6ij    = ps.y * pt.y;   // sqrt(C6_s C6_r)
    float Rij6    = ps.z * pt.z;   // R_s^3 R_r^3 = R_ij^6

    float r0 = 0.4f * sqrtRij + 4.0f;
    float q  = __fdividef(r0, r);
    float q2 = q * q, q4 = q2 * q2, q8 = q4 * q4;
    float q14 = q8 * q4 * q2;
    float fd = __fdividef(1.0f, 1.0f + 6.0f * q14);

    float r2 = r * r;
    float r6 = r2 * r2 * r2;
    float e = -C6ij * __fdividef(fd, Rij6 + r6);

    if (r >= 8.0f) {
        float x = (r - 8.0f) * 0.5f;
        float env = 0.0f;
        if (x < 1.0f) {
            float x2 = x * x;
            float x6 = x2 * x2 * x2;
            env = 1.0f + x6 * (-28.0f + x * (48.0f - 21.0f * x));
        }
        e *= env;
    }
    if (e != 0.0f) atomicAdd(&out[t], 0.5f * e);
}

__device__ __forceinline__ void edge_smem_setup(char* smem) {
    float4* s_par = (float4*)smem;
    if (threadIdx.x < NCLASS) {
        float2 p = c_raw[threadIdx.x];
        float4 o;
        o.x = sqrtf(sqrtf(p.x));
        o.y = sqrtf(p.y);
        o.z = p.x * p.x * p.x;
        o.w = 0.0f;
        s_par[threadIdx.x] = o;
    }
    const int4* src = (const int4*)g_class;
    int4* dst = (int4*)(smem + NCLASS * 16);
    for (int j = threadIdx.x; j < MAX_NODES / 16; j += blockDim.x) dst[j] = src[j];
    __syncthreads();
}

#define EDGE_SMEM (NCLASS * 16 + MAX_NODES)

// Phase 3: edge energies (vectorized, persistent grid-stride)
__global__ void __launch_bounds__(EDGE_BLOCK)
edge_kernel(const int* __restrict__ snd, const int* __restrict__ recv,
            const float* __restrict__ len, float* __restrict__ out,
            int n4, int n) {
    extern __shared__ char smem[];
    edge_smem_setup(smem);
    const float4* s_par = (const float4*)smem;
    const uint8_t* s_cls = (const uint8_t*)(smem + NCLASS * 16);

    const int4*   s4 = (const int4*)snd;
    const int4*   t4 = (const int4*)recv;
    const float4* r4 = (const float4*)len;
    int stride = gridDim.x * blockDim.x;
    for (int i = blockIdx.x * blockDim.x + threadIdx.x; i < n4; i += stride) {
        int4   s = s4[i];
        int4   t = t4[i];
        float4 r = r4[i];
        edge_one_sm(s_cls, s_par, s.x, t.x, r.x, out);
        edge_one_sm(s_cls, s_par, s.y, t.y, r.y, out);
        edge_one_sm(s_cls, s_par, s.z, t.z, r.z, out);
        edge_one_sm(s_cls, s_par, s.w, t.w, r.w, out);
    }
    if (blockIdx.x == 0 && threadIdx.x == 0) {
        for (int j = n4 * 4; j < n; j++)
            edge_one_sm(s_cls, s_par, snd[j], recv[j], len[j], out);
    }
}

// Scalar fallback (misaligned edge halves)
__global__ void __launch_bounds__(EDGE_BLOCK)
edge_kernel_scalar(const int* __restrict__ snd, const int* __restrict__ recv,
                   const float* __restrict__ len, float* __restrict__ out, int n) {
    extern __shared__ char smem[];
    edge_smem_setup(smem);
    const float4* s_par = (const float4*)smem;
    const uint8_t* s_cls = (const uint8_t*)(smem + NCLASS * 16);
    int stride = gridDim.x * blockDim.x;
    for (int i = blockIdx.x * blockDim.x + threadIdx.x; i < n; i += stride)
        edge_one_sm(s_cls, s_par, snd[i], recv[i], len[i], out);
}

extern "C" void kernel_launch(void* const* d_in, const int* in_sizes, int n_in,
                              void* d_out, int out_size) {
    const int*   Z   = (const int*)d_in[0];
    const int*   ei  = (const int*)d_in[1];
    const float* len = (const float*)d_in[2];
    float* out = (float*)d_out;

    int n_nodes = in_sizes[0];
    int n_edges = in_sizes[2];
    const int* snd  = ei;
    const int* recv = ei + n_edges;

    // Opt-in to >48KB dynamic smem (idempotent; not an allocation)
    static bool attr_done = false;
    if (!attr_done) {
        cudaFuncSetAttribute(count_kernel,
            cudaFuncAttributeMaxDynamicSharedMemorySize, MAX_NODES);
        cudaFuncSetAttribute(edge_kernel,
            cudaFuncAttributeMaxDynamicSharedMemorySize, EDGE_SMEM);
        cudaFuncSetAttribute(edge_kernel_scalar,
            cudaFuncAttributeMaxDynamicSharedMemorySize, EDGE_SMEM);
        attr_done = true;
    }

    const int TB = 256;
    zero_kernel<<<(n_nodes + TB - 1) / TB, TB>>>(out, Z, n_nodes);

    bool vec_ok = ((n_edges & 3) == 0);
    if (vec_ok) {
        int n4 = n_edges >> 2;
        count_kernel<<<PERS_GRID, EDGE_BLOCK, MAX_NODES>>>(recv, n4, n_edges);
        node_kernel<<<(n_nodes + TB - 1) / TB, TB>>>(Z, n_nodes);
        edge_kernel<<<PERS_GRID, EDGE_BLOCK, EDGE_SMEM>>>(snd, recv, len, out, n4, n_edges);
    } else {
        count_kernel_scalar<<<(n_edges + TB - 1) / TB, TB>>>(recv, n_edges);
        node_kernel<<<(n_nodes + TB - 1) / TB, TB>>>(Z, n_nodes);
        edge_kernel_scalar<<<PERS_GRID, EDGE_BLOCK, EDGE_SMEM>>>(snd, recv, len, out, n_edges);
    }
}